// round 1
// baseline (speedup 1.0000x reference)
#include <cuda_runtime.h>
#include <math_constants.h>

// Problem constants (from reference): B=8, U=V=13, H=128, W=160, TRUNC=4, MAX=6
#define UV 169          // 13*13
#define VDIM 13
#define HW 20480        // 128*160
#define PIX 128         // pixels per CTA (divides HW)
#define NTHREADS 128
#define SMEM_BYTES (UV * PIX * 4)   // 86528 B

__global__ __launch_bounds__(NTHREADS, 2)
void flow_regression_kernel(const float* __restrict__ x, float* __restrict__ out) {
    extern __shared__ float s[];   // [UV][PIX]

    const int tid   = threadIdx.x;
    const int blk   = blockIdx.x;          // 0 .. B*HW/PIX - 1  (= 1280)
    const int b     = blk / (HW / PIX);    // batch
    const int chunk = blk % (HW / PIX);    // 128-pixel chunk within (h,w) plane

    // base of this batch's tensor + pixel-chunk offset (all fits in int32)
    const float* xb = x + b * (UV * HW) + chunk * PIX;

    // ---- Load tile: 169 planes x 128 contiguous floats, float4-vectorized ----
    // UV * PIX/4 = 169*32 = 5408 float4 loads spread over 128 threads.
    #pragma unroll 4
    for (int i = tid; i < UV * (PIX / 4); i += NTHREADS) {
        int uv  = i >> 5;        // /32
        int off = i & 31;        // float4 index within plane chunk
        float4 v = *(const float4*)(xb + uv * HW + off * 4);
        *(float4*)(&s[uv * PIX + off * 4]) = v;
    }
    __syncthreads();

    // ---- Pass A: argmax over 169 channels (first-occurrence on ties) ----
    float m  = -CUDART_INF_F;
    int   am = 0;
    #pragma unroll 13
    for (int i = 0; i < UV; i++) {
        float v = s[i * PIX + tid];
        if (v > m) { m = v; am = i; }
    }
    const int ui = am / VDIM;
    const int vi = am - ui * VDIM;

    // ---- Pass B: masked softmax + expected displacement ----
    float Z = 0.0f, sU = 0.0f, sV = 0.0f;
    #pragma unroll
    for (int du = -4; du <= 4; du++) {
        int u = ui + du;
        if ((unsigned)u > 12u) continue;
        #pragma unroll
        for (int dv = -4; dv <= 4; dv++) {
            int v = vi + dv;
            if ((unsigned)v > 12u) continue;
            float e = __expf(s[(u * VDIM + v) * PIX + tid] - m);
            Z  += e;
            sU += e * (float)(u - 6);
            sV += e * (float)(v - 6);
        }
    }
    const float inv = __frcp_rn(Z);

    const int pix = chunk * PIX + tid;                 // index within (h,w) plane
    out[(b * 2 + 0) * HW + pix] = sU * inv;            // flowU
    out[(b * 2 + 1) * HW + pix] = sV * inv;            // flowV
}

extern "C" void kernel_launch(void* const* d_in, const int* in_sizes, int n_in,
                              void* d_out, int out_size) {
    (void)in_sizes; (void)n_in; (void)out_size;
    const float* x = (const float*)d_in[0];
    float* out = (float*)d_out;

    static bool attr_set = false;
    // cudaFuncSetAttribute is not a stream op; calling it unconditionally is
    // capture-safe, but only needed once for >48KB dynamic smem.
    cudaFuncSetAttribute(flow_regression_kernel,
                         cudaFuncAttributeMaxDynamicSharedMemorySize, SMEM_BYTES);
    (void)attr_set;

    const int nblocks = 8 * (HW / PIX);   // 1280
    flow_regression_kernel<<<nblocks, NTHREADS, SMEM_BYTES>>>(x, out);
}

// round 2
// speedup vs baseline: 1.9637x; 1.9637x over previous
#include <cuda_runtime.h>
#include <math_constants.h>

// B=8, U=V=13 (UV=169), H=128, W=160 (HW=20480), TRUNC=4, MAX disp=6
#define UV 169
#define VDIM 13
#define HW 20480
#define PIX 32                 // pixels per CTA
#define NTHREADS 128           // 4 threads cooperate per pixel
#define STRIDE 169             // smem row stride (floats) for s[pix][uv]
#define SMEM_BYTES (PIX * STRIDE * 4)   // 21632 B -> ~10 CTAs/SM

__global__ __launch_bounds__(NTHREADS)
void flow_regression_kernel(const float* __restrict__ x, float* __restrict__ out) {
    extern __shared__ float s[];   // s[pix][STRIDE], transposed tile

    const int tid   = threadIdx.x;
    const int blk   = blockIdx.x;            // 0 .. 8*640-1
    const int b     = blk / (HW / PIX);
    const int chunk = blk % (HW / PIX);      // 32-pixel chunk

    const float* xb = x + b * (UV * HW) + chunk * PIX;

    // ---- Load tile: 169 planes x 32 floats, float4 from gmem, transposed to smem ----
    // i in [0, 169*8): uv = i>>3, o = i&7 (float4 index within the 32-float chunk)
    #pragma unroll 4
    for (int i = tid; i < UV * (PIX / 4); i += NTHREADS) {
        int uv = i >> 3;
        int o  = i & 7;
        float4 v = *(const float4*)(xb + uv * HW + o * 4);
        int p0 = o * 4;
        s[(p0 + 0) * STRIDE + uv] = v.x;
        s[(p0 + 1) * STRIDE + uv] = v.y;
        s[(p0 + 2) * STRIDE + uv] = v.z;
        s[(p0 + 3) * STRIDE + uv] = v.w;
    }
    __syncthreads();

    const int sub = tid & 3;        // 0..3, which quarter of the work
    const int p   = tid >> 2;       // 0..31, pixel within chunk
    const float* sp = s + p * STRIDE;

    // ---- Pass A: argmax over 169 channels, 4-way split + shfl reduce ----
    float m  = -CUDART_INF_F;
    int   am = 0;
    #pragma unroll 8
    for (int uv = sub; uv < UV; uv += 4) {
        float v = sp[uv];
        if (v > m) { m = v; am = uv; }
    }
    // combine across the 4 lanes of this pixel (first-occurrence tie-break)
    #pragma unroll
    for (int off = 1; off <= 2; off <<= 1) {
        float mo = __shfl_xor_sync(0xffffffffu, m,  off);
        int   ao = __shfl_xor_sync(0xffffffffu, am, off);
        if (mo > m || (mo == m && ao < am)) { m = mo; am = ao; }
    }
    const int ui = am / VDIM;
    const int vi = am - ui * VDIM;

    // ---- Pass B: 9x9 truncated-window softmax, 4-way split ----
    float Z = 0.0f, sU = 0.0f, sV = 0.0f;
    #pragma unroll 6
    for (int k = sub; k < 81; k += 4) {
        int du = (k / 9) - 4;
        int dv = (k % 9) - 4;
        int u = ui + du;
        int v = vi + dv;
        if ((unsigned)u <= 12u && (unsigned)v <= 12u) {
            float e = __expf(sp[u * VDIM + v] - m);
            Z  += e;
            sU += e * (float)(u - 6);
            sV += e * (float)(v - 6);
        }
    }
    #pragma unroll
    for (int off = 1; off <= 2; off <<= 1) {
        Z  += __shfl_xor_sync(0xffffffffu, Z,  off);
        sU += __shfl_xor_sync(0xffffffffu, sU, off);
        sV += __shfl_xor_sync(0xffffffffu, sV, off);
    }

    if (sub == 0) {
        const float inv = __frcp_rn(Z);
        const int pix = chunk * PIX + p;
        out[(b * 2 + 0) * HW + pix] = sU * inv;
        out[(b * 2 + 1) * HW + pix] = sV * inv;
    }
}

extern "C" void kernel_launch(void* const* d_in, const int* in_sizes, int n_in,
                              void* d_out, int out_size) {
    (void)in_sizes; (void)n_in; (void)out_size;
    const float* x = (const float*)d_in[0];
    float* out = (float*)d_out;

    const int nblocks = 8 * (HW / PIX);   // 5120
    flow_regression_kernel<<<nblocks, NTHREADS, SMEM_BYTES>>>(x, out);
}